// round 2
// baseline (speedup 1.0000x reference)
#include <cuda_runtime.h>

namespace {
constexpr int T_STEPS = 256;
constexpr int B_SZ    = 4096;
constexpr int HID     = 64;
constexpr int MLPW    = 128;
constexpr int DOUT    = 8;
constexpr int R_ROWS  = 4;    // batch rows per warp
constexpr int NWARPS  = 8;    // warps per CTA
constexpr int NSTEP   = 255;
constexpr int ROWS_PER_CTA = R_ROWS * NWARPS;   // 32
constexpr int NCTA = B_SZ / ROWS_PER_CTA;       // 128
}

__device__ __forceinline__ float4 ldg4(const float* p) {
    return __ldg(reinterpret_cast<const float4*>(p));
}
__device__ __forceinline__ float2 ldg2(const float* p) {
    return __ldg(reinterpret_cast<const float2*>(p));
}
__device__ __forceinline__ float lipswish(float x) {
    float s = 1.0f / (1.0f + __expf(-x));
    return 0.909f * x * s;
}
__device__ __forceinline__ float f4c(const float4& v, int kk) {
    return kk == 0 ? v.x : kk == 1 ? v.y : kk == 2 ? v.z : v.w;
}

// acc[R][4] += src(R x K) * W(K x 128), lane owns columns 4*lane..4*lane+3
template<int K, int SSTRIDE>
__device__ __forceinline__ void gemm_n128(const float* __restrict__ W,
                                          const float* __restrict__ src,
                                          float acc[R_ROWS][4], int lane)
{
    const float* Wp = W + 4 * lane;
#pragma unroll 4
    for (int kb = 0; kb < K / 4; kb++) {
        float4 a[R_ROWS];
#pragma unroll
        for (int r = 0; r < R_ROWS; r++)
            a[r] = *reinterpret_cast<const float4*>(src + r * SSTRIDE + kb * 4);
        float4 wv[4];
#pragma unroll
        for (int kk = 0; kk < 4; kk++)
            wv[kk] = ldg4(Wp + (kb * 4 + kk) * MLPW);
#pragma unroll
        for (int r = 0; r < R_ROWS; r++) {
#pragma unroll
            for (int kk = 0; kk < 4; kk++) {
                float av = f4c(a[r], kk);
                acc[r][0] = fmaf(av, wv[kk].x, acc[r][0]);
                acc[r][1] = fmaf(av, wv[kk].y, acc[r][1]);
                acc[r][2] = fmaf(av, wv[kk].z, acc[r][2]);
                acc[r][3] = fmaf(av, wv[kk].w, acc[r][3]);
            }
        }
    }
}

// acc[R][2] += src(R x K) * W(K x 64), lane owns columns 2*lane..2*lane+1
template<int K, int SSTRIDE>
__device__ __forceinline__ void gemm_n64(const float* __restrict__ W,
                                         const float* __restrict__ src,
                                         float acc[R_ROWS][2], int lane)
{
    const float* Wp = W + 2 * lane;
#pragma unroll 4
    for (int kb = 0; kb < K / 4; kb++) {
        float4 a[R_ROWS];
#pragma unroll
        for (int r = 0; r < R_ROWS; r++)
            a[r] = *reinterpret_cast<const float4*>(src + r * SSTRIDE + kb * 4);
        float2 wv[4];
#pragma unroll
        for (int kk = 0; kk < 4; kk++)
            wv[kk] = ldg2(Wp + (kb * 4 + kk) * HID);
#pragma unroll
        for (int r = 0; r < R_ROWS; r++) {
#pragma unroll
            for (int kk = 0; kk < 4; kk++) {
                float av = f4c(a[r], kk);
                acc[r][0] = fmaf(av, wv[kk].x, acc[r][0]);
                acc[r][1] = fmaf(av, wv[kk].y, acc[r][1]);
            }
        }
    }
}

// One full MLP: tx = [t, x(64)] -> lipswish -> lipswish -> tanh. Output in
// outv[r][s] for hidden index h = 2*lane + s (matches the state register layout).
__device__ __forceinline__ void mlp_eval(
    float tn,
    const float* __restrict__ W0, const float* __restrict__ b0,
    const float* __restrict__ W1, const float* __restrict__ b1,
    const float* __restrict__ Wo, const float* __restrict__ bo,
    const float* __restrict__ sIn,   // [R_ROWS][HID]  (x part of tx)
    float* __restrict__ sH1,         // [R_ROWS][MLPW]
    float* __restrict__ sH2,         // [R_ROWS][MLPW]
    float outv[R_ROWS][2], int lane)
{
    float acc[R_ROWS][4];
    {   // bias + t * W0_row0 (tx[0] = t is uniform across rows and lanes)
        float4 bv = ldg4(b0 + 4 * lane);
        float4 w0 = ldg4(W0 + 4 * lane);
#pragma unroll
        for (int r = 0; r < R_ROWS; r++) {
            acc[r][0] = fmaf(tn, w0.x, bv.x);
            acc[r][1] = fmaf(tn, w0.y, bv.y);
            acc[r][2] = fmaf(tn, w0.z, bv.z);
            acc[r][3] = fmaf(tn, w0.w, bv.w);
        }
    }
    gemm_n128<HID, HID>(W0 + MLPW, sIn, acc, lane);   // rows 1..64 of W0
#pragma unroll
    for (int r = 0; r < R_ROWS; r++) {
        float4 o;
        o.x = lipswish(acc[r][0]); o.y = lipswish(acc[r][1]);
        o.z = lipswish(acc[r][2]); o.w = lipswish(acc[r][3]);
        *reinterpret_cast<float4*>(sH1 + r * MLPW + 4 * lane) = o;
    }
    __syncwarp();

    {
        float4 bv = ldg4(b1 + 4 * lane);
#pragma unroll
        for (int r = 0; r < R_ROWS; r++) {
            acc[r][0] = bv.x; acc[r][1] = bv.y; acc[r][2] = bv.z; acc[r][3] = bv.w;
        }
    }
    gemm_n128<MLPW, MLPW>(W1, sH1, acc, lane);
#pragma unroll
    for (int r = 0; r < R_ROWS; r++) {
        float4 o;
        o.x = lipswish(acc[r][0]); o.y = lipswish(acc[r][1]);
        o.z = lipswish(acc[r][2]); o.w = lipswish(acc[r][3]);
        *reinterpret_cast<float4*>(sH2 + r * MLPW + 4 * lane) = o;
    }
    __syncwarp();

    float acc2[R_ROWS][2];
    {
        float2 bv = ldg2(bo + 2 * lane);
#pragma unroll
        for (int r = 0; r < R_ROWS; r++) { acc2[r][0] = bv.x; acc2[r][1] = bv.y; }
    }
    gemm_n64<MLPW, MLPW>(Wo, sH2, acc2, lane);
#pragma unroll
    for (int r = 0; r < R_ROWS; r++) {
        outv[r][0] = tanhf(acc2[r][0]);
        outv[r][1] = tanhf(acc2[r][1]);
    }
}

// lane (r = lane>>3, d = lane&7): ys[r][d] = rb[d] + z[r,:] @ RW[:,d]
__device__ __forceinline__ void readout_store(
    const float* __restrict__ myZ,          // [R_ROWS][HID] holds z
    const float (*sRWt)[68], const float* __restrict__ sRB,
    float* __restrict__ out, int rowbase, int tIdx, float tval, int lane)
{
    const int r = lane >> 3;
    const int d = lane & 7;
    float acc = sRB[d];
#pragma unroll
    for (int hb = 0; hb < HID / 4; hb++) {
        float4 zv = *reinterpret_cast<const float4*>(myZ + r * HID + hb * 4);
        float4 wv = *reinterpret_cast<const float4*>(&sRWt[d][hb * 4]);
        acc = fmaf(zv.x, wv.x, acc);
        acc = fmaf(zv.y, wv.y, acc);
        acc = fmaf(zv.z, wv.z, acc);
        acc = fmaf(zv.w, wv.w, acc);
    }
    size_t base = ((size_t)(rowbase + r) * T_STEPS + tIdx) * (DOUT + 1);
    out[base + 1 + d] = acc;
    if (d == 0) out[base] = tval;
}

__global__ void __launch_bounds__(NWARPS * 32, 1)
sde_kernel(const float* __restrict__ ts,
           const float* __restrict__ dW,
           const float* __restrict__ dW0, const float* __restrict__ db0,
           const float* __restrict__ dW1, const float* __restrict__ db1,
           const float* __restrict__ dWo, const float* __restrict__ dbo,
           const float* __restrict__ fW0, const float* __restrict__ fb0,
           const float* __restrict__ fW1, const float* __restrict__ fb1,
           const float* __restrict__ fWo, const float* __restrict__ fbo,
           const float* __restrict__ RW, const float* __restrict__ rb,
           float* __restrict__ out)
{
    __shared__ float sZ [NWARPS][R_ROWS][HID];   // 8 KB  (x / zhat / z staging)
    __shared__ float sH1[NWARPS][R_ROWS][MLPW];  // 16 KB
    __shared__ float sH2[NWARPS][R_ROWS][MLPW];  // 16 KB
    __shared__ float sRWt[DOUT][68];             // readout W, transposed + padded
    __shared__ float sRB[DOUT];

    const int tid  = threadIdx.x;
    const int w    = tid >> 5;
    const int lane = tid & 31;

    for (int i = tid; i < HID * DOUT; i += blockDim.x)
        sRWt[i & 7][i >> 3] = __ldg(RW + i);     // RW is (64, 8) row-major
    if (tid < DOUT) sRB[tid] = __ldg(rb + tid);
    __syncthreads();

    const int rowbase = (blockIdx.x * NWARPS + w) * R_ROWS;
    const float t0  = __ldg(ts + 0);
    const float dt  = __ldg(ts + 1) - t0;
    const float sdt = sqrtf(dt);

    float z[R_ROWS][2], zh[R_ROWS][2], f[R_ROWS][2], g[R_ROWS][2], dwc[R_ROWS][2];

    float* myZ  = &sZ[w][0][0];
    float* myH1 = &sH1[w][0][0];
    float* myH2 = &sH2[w][0][0];

#pragma unroll
    for (int r = 0; r < R_ROWS; r++) {
        z[r][0] = z[r][1] = 1.0f;
        zh[r][0] = zh[r][1] = 1.0f;
        *reinterpret_cast<float2*>(myZ + r * HID + 2 * lane) = make_float2(1.0f, 1.0f);
    }
    __syncwarp();

    // f0, g0 at t = ts[0], x0 = ones
    mlp_eval(t0, dW0, db0, dW1, db1, dWo, dbo, myZ, myH1, myH2, f, lane);
    mlp_eval(t0, fW0, fb0, fW1, fb1, fWo, fbo, myZ, myH1, myH2, g, lane);

    // t = 0 output (myZ still holds x0 = ones)
    readout_store(myZ, sRWt, sRB, out, rowbase, 0, t0, lane);

    // Brownian increments for step 0 (pre-scaled by sqrt(dt))
#pragma unroll
    for (int r = 0; r < R_ROWS; r++) {
        float2 v = ldg2(dW + (size_t)(rowbase + r) * HID + 2 * lane);
        dwc[r][0] = v.x * sdt; dwc[r][1] = v.y * sdt;
    }
    __syncwarp();

    for (int n = 0; n < NSTEP; n++) {
        const float tn = __ldg(ts + n + 1);

        // zhat_{n+1} = 2 z - zhat + f dt + g dw ; stage into shared for the MLPs
#pragma unroll
        for (int r = 0; r < R_ROWS; r++) {
#pragma unroll
            for (int s = 0; s < 2; s++)
                zh[r][s] = 2.0f * z[r][s] - zh[r][s] + f[r][s] * dt + g[r][s] * dwc[r][s];
            *reinterpret_cast<float2*>(myZ + r * HID + 2 * lane) =
                make_float2(zh[r][0], zh[r][1]);
        }
        __syncwarp();

        float fn[R_ROWS][2], gn[R_ROWS][2];
        mlp_eval(tn, dW0, db0, dW1, db1, dWo, dbo, myZ, myH1, myH2, fn, lane);
        mlp_eval(tn, fW0, fb0, fW1, fb1, fWo, fbo, myZ, myH1, myH2, gn, lane);

        // z_{n+1} = z + 0.5 (f + fn) dt + 0.5 (g + gn) dw
#pragma unroll
        for (int r = 0; r < R_ROWS; r++) {
#pragma unroll
            for (int s = 0; s < 2; s++) {
                z[r][s] += 0.5f * (f[r][s] + fn[r][s]) * dt
                         + 0.5f * (g[r][s] + gn[r][s]) * dwc[r][s];
                f[r][s] = fn[r][s];
                g[r][s] = gn[r][s];
            }
        }

        // prefetch next step's dW while the readout below runs
        if (n + 1 < NSTEP) {
#pragma unroll
            for (int r = 0; r < R_ROWS; r++) {
                float2 v = ldg2(dW + ((size_t)(n + 1) * B_SZ + (rowbase + r)) * HID + 2 * lane);
                dwc[r][0] = v.x * sdt; dwc[r][1] = v.y * sdt;
            }
        }

        __syncwarp();
#pragma unroll
        for (int r = 0; r < R_ROWS; r++)
            *reinterpret_cast<float2*>(myZ + r * HID + 2 * lane) =
                make_float2(z[r][0], z[r][1]);
        __syncwarp();

        readout_store(myZ, sRWt, sRB, out, rowbase, n + 1, tn, lane);
        __syncwarp();
    }
}

extern "C" void kernel_launch(void* const* d_in, const int* in_sizes, int n_in,
                              void* d_out, int out_size) {
    (void)in_sizes; (void)n_in; (void)out_size;
    const float* ts  = (const float*)d_in[0];
    // d_in[1] = batch_size (int32 scalar) — shapes are fixed constants here
    const float* dW  = (const float*)d_in[2];
    const float* dW0 = (const float*)d_in[3];
    const float* db0 = (const float*)d_in[4];
    const float* dW1 = (const float*)d_in[5];
    const float* db1 = (const float*)d_in[6];
    const float* dWo = (const float*)d_in[7];
    const float* dbo = (const float*)d_in[8];
    const float* fW0 = (const float*)d_in[9];
    const float* fb0 = (const float*)d_in[10];
    const float* fW1 = (const float*)d_in[11];
    const float* fb1 = (const float*)d_in[12];
    const float* fWo = (const float*)d_in[13];
    const float* fbo = (const float*)d_in[14];
    const float* RW  = (const float*)d_in[15];
    const float* rb  = (const float*)d_in[16];
    float* out = (float*)d_out;

    sde_kernel<<<NCTA, NWARPS * 32>>>(ts, dW,
                                      dW0, db0, dW1, db1, dWo, dbo,
                                      fW0, fb0, fW1, fb1, fWo, fbo,
                                      RW, rb, out);
}

// round 3
// speedup vs baseline: 1.1697x; 1.1697x over previous
#include <cuda_runtime.h>

namespace {
constexpr int T_STEPS = 256;
constexpr int B_SZ    = 4096;
constexpr int HID     = 64;
constexpr int MLPW    = 128;
constexpr int DOUT    = 8;
constexpr int R_ROWS  = 4;    // batch rows per warp
constexpr int NWARPS  = 7;    // warps per CTA
constexpr int NSTEP   = 255;
constexpr int NCTA    = 148;  // full chip; 148*7*4 = 4144 >= 4096, tail warps exit
}

using ull = unsigned long long;

__device__ __forceinline__ ull fma2(ull a, ull b, ull c) {
    ull d;
    asm("fma.rn.f32x2 %0, %1, %2, %3;" : "=l"(d) : "l"(a), "l"(b), "l"(c));
    return d;
}
__device__ __forceinline__ ull splat2(float x) {
    ull d;
    unsigned u = __float_as_uint(x);
    asm("mov.b64 %0, {%1, %1};" : "=l"(d) : "r"(u));
    return d;
}
__device__ __forceinline__ float2 unpack2(ull v) {
    float2 r;
    asm("mov.b64 {%0, %1}, %2;" : "=f"(r.x), "=f"(r.y) : "l"(v));
    return r;
}
__device__ __forceinline__ ull pack2(float a, float b) {
    ull d;
    unsigned ua = __float_as_uint(a), ub = __float_as_uint(b);
    asm("mov.b64 %0, {%1, %2};" : "=l"(d) : "r"(ua), "r"(ub));
    return d;
}
__device__ __forceinline__ float2 ldg2f(const float* p) {
    return __ldg(reinterpret_cast<const float2*>(p));
}
__device__ __forceinline__ float lipswish(float x) {
    float s = 1.0f / (1.0f + __expf(-x));
    return 0.909f * x * s;
}

// acc[r][0] covers cols (4l,4l+1), acc[r][1] covers (4l+2,4l+3).
// aS: per-row splatted activations, [r][K] ull, row stride K.
template<int K>
__device__ __forceinline__ void gemm128_f2(const float* __restrict__ W,   // K x 128
                                           const ull* __restrict__ aS,
                                           ull acc[R_ROWS][2], int lane)
{
    const float* Wp = W + 4 * lane;
#pragma unroll 4
    for (int kb = 0; kb < K / 4; kb++) {
        ulonglong2 a0[R_ROWS], a1[R_ROWS];
#pragma unroll
        for (int r = 0; r < R_ROWS; r++) {
            a0[r] = *reinterpret_cast<const ulonglong2*>(aS + r * K + kb * 4);
            a1[r] = *reinterpret_cast<const ulonglong2*>(aS + r * K + kb * 4 + 2);
        }
        ulonglong2 wv[4];
#pragma unroll
        for (int kk = 0; kk < 4; kk++)
            wv[kk] = __ldg(reinterpret_cast<const ulonglong2*>(Wp + (kb * 4 + kk) * MLPW));
#pragma unroll
        for (int r = 0; r < R_ROWS; r++) {
            acc[r][0] = fma2(a0[r].x, wv[0].x, acc[r][0]);
            acc[r][1] = fma2(a0[r].x, wv[0].y, acc[r][1]);
            acc[r][0] = fma2(a0[r].y, wv[1].x, acc[r][0]);
            acc[r][1] = fma2(a0[r].y, wv[1].y, acc[r][1]);
            acc[r][0] = fma2(a1[r].x, wv[2].x, acc[r][0]);
            acc[r][1] = fma2(a1[r].x, wv[2].y, acc[r][1]);
            acc[r][0] = fma2(a1[r].y, wv[3].x, acc[r][0]);
            acc[r][1] = fma2(a1[r].y, wv[3].y, acc[r][1]);
        }
    }
}

// Output layer: N=64, lane owns cols (2l,2l+1) -> one packed acc per row.
template<int K>
__device__ __forceinline__ void gemm64_f2(const float* __restrict__ W,    // K x 64
                                          const ull* __restrict__ aS,
                                          ull acc[R_ROWS], int lane)
{
    const float* Wp = W + 2 * lane;
#pragma unroll 4
    for (int kb = 0; kb < K / 4; kb++) {
        ulonglong2 a0[R_ROWS], a1[R_ROWS];
#pragma unroll
        for (int r = 0; r < R_ROWS; r++) {
            a0[r] = *reinterpret_cast<const ulonglong2*>(aS + r * K + kb * 4);
            a1[r] = *reinterpret_cast<const ulonglong2*>(aS + r * K + kb * 4 + 2);
        }
        ull wv[4];
#pragma unroll
        for (int kk = 0; kk < 4; kk++)
            wv[kk] = __ldg(reinterpret_cast<const ull*>(Wp + (kb * 4 + kk) * HID));
#pragma unroll
        for (int r = 0; r < R_ROWS; r++) {
            acc[r] = fma2(a0[r].x, wv[0], acc[r]);
            acc[r] = fma2(a0[r].y, wv[1], acc[r]);
            acc[r] = fma2(a1[r].x, wv[2], acc[r]);
            acc[r] = fma2(a1[r].y, wv[3], acc[r]);
        }
    }
}

// Full MLP: tx=[t, x(64)] -> lipswish -> lipswish -> tanh.
// zhS: [R][HID] splatted input. hS: [R][MLPW] splatted scratch (used in-place
// for h1 then h2). outv[r][s] for hidden h = 2*lane + s.
__device__ __forceinline__ void mlp_eval(
    float tn,
    const float* __restrict__ W0, const float* __restrict__ b0,
    const float* __restrict__ W1, const float* __restrict__ b1,
    const float* __restrict__ Wo, const float* __restrict__ bo,
    const ull* __restrict__ zhS, ull* __restrict__ hS,
    float outv[R_ROWS][2], int lane)
{
    ull acc[R_ROWS][2];
    {   // bias + t * W0_row0
        ulonglong2 bv = __ldg(reinterpret_cast<const ulonglong2*>(b0 + 4 * lane));
        ulonglong2 w0 = __ldg(reinterpret_cast<const ulonglong2*>(W0 + 4 * lane));
        ull t2 = splat2(tn);
#pragma unroll
        for (int r = 0; r < R_ROWS; r++) {
            acc[r][0] = fma2(t2, w0.x, bv.x);
            acc[r][1] = fma2(t2, w0.y, bv.y);
        }
    }
    gemm128_f2<HID>(W0 + MLPW, zhS, acc, lane);   // rows 1..64 of W0
#pragma unroll
    for (int r = 0; r < R_ROWS; r++) {
        float2 p0 = unpack2(acc[r][0]), p1 = unpack2(acc[r][1]);
        float h0 = lipswish(p0.x), h1 = lipswish(p0.y);
        float h2 = lipswish(p1.x), h3 = lipswish(p1.y);
        ulonglong2 s0, s1;
        s0.x = splat2(h0); s0.y = splat2(h1);
        s1.x = splat2(h2); s1.y = splat2(h3);
        *reinterpret_cast<ulonglong2*>(hS + r * MLPW + 4 * lane) = s0;
        *reinterpret_cast<ulonglong2*>(hS + r * MLPW + 4 * lane + 2) = s1;
    }
    __syncwarp();

    {
        ulonglong2 bv = __ldg(reinterpret_cast<const ulonglong2*>(b1 + 4 * lane));
#pragma unroll
        for (int r = 0; r < R_ROWS; r++) { acc[r][0] = bv.x; acc[r][1] = bv.y; }
    }
    gemm128_f2<MLPW>(W1, hS, acc, lane);
    __syncwarp();   // all reads of h1 done before overwriting in place
#pragma unroll
    for (int r = 0; r < R_ROWS; r++) {
        float2 p0 = unpack2(acc[r][0]), p1 = unpack2(acc[r][1]);
        float h0 = lipswish(p0.x), h1 = lipswish(p0.y);
        float h2 = lipswish(p1.x), h3 = lipswish(p1.y);
        ulonglong2 s0, s1;
        s0.x = splat2(h0); s0.y = splat2(h1);
        s1.x = splat2(h2); s1.y = splat2(h3);
        *reinterpret_cast<ulonglong2*>(hS + r * MLPW + 4 * lane) = s0;
        *reinterpret_cast<ulonglong2*>(hS + r * MLPW + 4 * lane + 2) = s1;
    }
    __syncwarp();

    ull acc2[R_ROWS];
    {
        ull bv = __ldg(reinterpret_cast<const ull*>(bo + 2 * lane));
#pragma unroll
        for (int r = 0; r < R_ROWS; r++) acc2[r] = bv;
    }
    gemm64_f2<MLPW>(Wo, hS, acc2, lane);
#pragma unroll
    for (int r = 0; r < R_ROWS; r++) {
        float2 p = unpack2(acc2[r]);
        outv[r][0] = tanhf(p.x);
        outv[r][1] = tanhf(p.y);
    }
}

// lane (r = lane>>3, d = lane&7): ys[r][d] = rb[d] + z[r,:] @ RW[:,d]
__device__ __forceinline__ void readout_store(
    const float* __restrict__ zc,           // [R_ROWS][HID] compact z
    const float (*sRWt)[68], const float* __restrict__ sRB,
    float* __restrict__ out, int rowbase, int tIdx, float tval, int lane)
{
    const int r = lane >> 3;
    const int d = lane & 7;
    float acc = sRB[d];
#pragma unroll
    for (int hb = 0; hb < HID / 4; hb++) {
        float4 zv = *reinterpret_cast<const float4*>(zc + r * HID + hb * 4);
        float4 wv = *reinterpret_cast<const float4*>(&sRWt[d][hb * 4]);
        acc = fmaf(zv.x, wv.x, acc);
        acc = fmaf(zv.y, wv.y, acc);
        acc = fmaf(zv.z, wv.z, acc);
        acc = fmaf(zv.w, wv.w, acc);
    }
    size_t base = ((size_t)(rowbase + r) * T_STEPS + tIdx) * (DOUT + 1);
    out[base + 1 + d] = acc;
    if (d == 0) out[base] = tval;
}

__global__ void __launch_bounds__(NWARPS * 32, 1)
sde_kernel(const float* __restrict__ ts,
           const float* __restrict__ dW,
           const float* __restrict__ dW0, const float* __restrict__ db0,
           const float* __restrict__ dW1, const float* __restrict__ db1,
           const float* __restrict__ dWo, const float* __restrict__ dbo,
           const float* __restrict__ fW0, const float* __restrict__ fb0,
           const float* __restrict__ fW1, const float* __restrict__ fb1,
           const float* __restrict__ fWo, const float* __restrict__ fbo,
           const float* __restrict__ RW, const float* __restrict__ rb,
           float* __restrict__ out)
{
    __shared__ ull  sZh[NWARPS][R_ROWS][HID];    // splatted zhat: 14 KB
    __shared__ ull  sH [NWARPS][R_ROWS][MLPW];   // splatted h (in-place h1/h2): 28 KB
    __shared__ float sRWt[DOUT][68];
    __shared__ float sRB[DOUT];

    const int tid  = threadIdx.x;
    const int w    = tid >> 5;
    const int lane = tid & 31;

    for (int i = tid; i < HID * DOUT; i += blockDim.x)
        sRWt[i & 7][i >> 3] = __ldg(RW + i);     // RW is (64, 8) row-major
    if (tid < DOUT) sRB[tid] = __ldg(rb + tid);
    __syncthreads();

    const int rowbase = (blockIdx.x * NWARPS + w) * R_ROWS;
    if (rowbase >= B_SZ) return;                 // tail warps (12 of 1036) idle

    const float t0  = __ldg(ts + 0);
    const float dt  = __ldg(ts + 1) - t0;
    const float sdt = sqrtf(dt);

    float z[R_ROWS][2], zh[R_ROWS][2], f[R_ROWS][2], g[R_ROWS][2], dwc[R_ROWS][2];

    ull*  zhS = &sZh[w][0][0];
    ull*  hS  = &sH [w][0][0];
    float* zc = reinterpret_cast<float*>(hS);    // compact z for readout (aliases hS)

    const ull one2 = splat2(1.0f);
#pragma unroll
    for (int r = 0; r < R_ROWS; r++) {
        z[r][0] = z[r][1] = 1.0f;
        zh[r][0] = zh[r][1] = 1.0f;
        zhS[r * HID + 2 * lane]     = one2;
        zhS[r * HID + 2 * lane + 1] = one2;
    }
    __syncwarp();

    // f0, g0 at t = ts[0], x0 = ones
    mlp_eval(t0, dW0, db0, dW1, db1, dWo, dbo, zhS, hS, f, lane);
    __syncwarp();
    mlp_eval(t0, fW0, fb0, fW1, fb1, fWo, fbo, zhS, hS, g, lane);
    __syncwarp();

    // t = 0 readout: z = ones (write compact z over hS, now dead)
#pragma unroll
    for (int r = 0; r < R_ROWS; r++)
        *reinterpret_cast<float2*>(zc + r * HID + 2 * lane) = make_float2(1.0f, 1.0f);
    __syncwarp();
    readout_store(zc, sRWt, sRB, out, rowbase, 0, t0, lane);

    // Brownian increments for step 0 (pre-scaled by sqrt(dt))
#pragma unroll
    for (int r = 0; r < R_ROWS; r++) {
        float2 v = ldg2f(dW + (size_t)(rowbase + r) * HID + 2 * lane);
        dwc[r][0] = v.x * sdt; dwc[r][1] = v.y * sdt;
    }
    __syncwarp();

    for (int n = 0; n < NSTEP; n++) {
        const float tn = __ldg(ts + n + 1);

        // zhat_{n+1} = 2 z - zhat + f dt + g dw ; stage splatted for the MLPs
#pragma unroll
        for (int r = 0; r < R_ROWS; r++) {
#pragma unroll
            for (int s = 0; s < 2; s++)
                zh[r][s] = 2.0f * z[r][s] - zh[r][s] + f[r][s] * dt + g[r][s] * dwc[r][s];
            ulonglong2 zs;
            zs.x = splat2(zh[r][0]); zs.y = splat2(zh[r][1]);
            *reinterpret_cast<ulonglong2*>(zhS + r * HID + 2 * lane) = zs;
        }
        __syncwarp();

        float fn[R_ROWS][2], gn[R_ROWS][2];
        mlp_eval(tn, dW0, db0, dW1, db1, dWo, dbo, zhS, hS, fn, lane);
        __syncwarp();
        mlp_eval(tn, fW0, fb0, fW1, fb1, fWo, fbo, zhS, hS, gn, lane);
        __syncwarp();

        // z_{n+1} = z + 0.5 (f + fn) dt + 0.5 (g + gn) dw
#pragma unroll
        for (int r = 0; r < R_ROWS; r++) {
#pragma unroll
            for (int s = 0; s < 2; s++) {
                z[r][s] += 0.5f * (f[r][s] + fn[r][s]) * dt
                         + 0.5f * (g[r][s] + gn[r][s]) * dwc[r][s];
                f[r][s] = fn[r][s];
                g[r][s] = gn[r][s];
            }
        }

        // prefetch next step's dW
        if (n + 1 < NSTEP) {
#pragma unroll
            for (int r = 0; r < R_ROWS; r++) {
                float2 v = ldg2f(dW + ((size_t)(n + 1) * B_SZ + (rowbase + r)) * HID + 2 * lane);
                dwc[r][0] = v.x * sdt; dwc[r][1] = v.y * sdt;
            }
        }

        // compact z into (dead) hS region for the readout
#pragma unroll
        for (int r = 0; r < R_ROWS; r++)
            *reinterpret_cast<float2*>(zc + r * HID + 2 * lane) =
                make_float2(z[r][0], z[r][1]);
        __syncwarp();

        readout_store(zc, sRWt, sRB, out, rowbase, n + 1, tn, lane);
        __syncwarp();
    }
}

extern "C" void kernel_launch(void* const* d_in, const int* in_sizes, int n_in,
                              void* d_out, int out_size) {
    (void)in_sizes; (void)n_in; (void)out_size;
    const float* ts  = (const float*)d_in[0];
    // d_in[1] = batch_size (int32 scalar) — shapes are fixed constants here
    const float* dW  = (const float*)d_in[2];
    const float* dW0 = (const float*)d_in[3];
    const float* db0 = (const float*)d_in[4];
    const float* dW1 = (const float*)d_in[5];
    const float* db1 = (const float*)d_in[6];
    const float* dWo = (const float*)d_in[7];
    const float* dbo = (const float*)d_in[8];
    const float* fW0 = (const float*)d_in[9];
    const float* fb0 = (const float*)d_in[10];
    const float* fW1 = (const float*)d_in[11];
    const float* fb1 = (const float*)d_in[12];
    const float* fWo = (const float*)d_in[13];
    const float* fbo = (const float*)d_in[14];
    const float* RW  = (const float*)d_in[15];
    const float* rb  = (const float*)d_in[16];
    float* out = (float*)d_out;

    sde_kernel<<<NCTA, NWARPS * 32>>>(ts, dW,
                                      dW0, db0, dW1, db1, dWo, dbo,
                                      fW0, fb0, fW1, fb1, fWo, fbo,
                                      RW, rb, out);
}

// round 4
// speedup vs baseline: 1.1719x; 1.0019x over previous
#include <cuda_runtime.h>

namespace {
constexpr int T_STEPS = 256;
constexpr int B_SZ    = 4096;
constexpr int HID     = 64;
constexpr int MLPW    = 128;
constexpr int DOUT    = 8;
constexpr int R_ROWS  = 4;    // batch rows per warp
constexpr int NWARPS  = 7;    // warps per CTA
constexpr int NSTEP   = 255;
constexpr int NCTA    = 148;  // full chip; 148*7*4 = 4144 >= 4096, tail warps exit
}

using ull = unsigned long long;

__device__ __forceinline__ ull fma2(ull a, ull b, ull c) {
    ull d;
    asm("fma.rn.f32x2 %0, %1, %2, %3;" : "=l"(d) : "l"(a), "l"(b), "l"(c));
    return d;
}
__device__ __forceinline__ ull splat2(float x) {
    ull d;
    unsigned u = __float_as_uint(x);
    asm("mov.b64 %0, {%1, %1};" : "=l"(d) : "r"(u));
    return d;
}
__device__ __forceinline__ float2 unpack2(ull v) {
    float2 r;
    asm("mov.b64 {%0, %1}, %2;" : "=f"(r.x), "=f"(r.y) : "l"(v));
    return r;
}
__device__ __forceinline__ ull pack2(float a, float b) {
    ull d;
    unsigned ua = __float_as_uint(a), ub = __float_as_uint(b);
    asm("mov.b64 %0, {%1, %2};" : "=l"(d) : "r"(ua), "r"(ub));
    return d;
}
__device__ __forceinline__ float2 ldg2f(const float* p) {
    return __ldg(reinterpret_cast<const float2*>(p));
}
__device__ __forceinline__ float lipswish(float x) {
    float s = 1.0f / (1.0f + __expf(-x));
    return 0.909f * x * s;
}

// acc[r][0] covers cols (4l,4l+1), acc[r][1] covers (4l+2,4l+3).
// aS: per-row splatted activations, [r][K] ull, row stride K.
template<int K>
__device__ __forceinline__ void gemm128_f2(const float* __restrict__ W,   // K x 128
                                           const ull* __restrict__ aS,
                                           ull acc[R_ROWS][2], int lane)
{
    const float* Wp = W + 4 * lane;
#pragma unroll 4
    for (int kb = 0; kb < K / 4; kb++) {
        ulonglong2 a0[R_ROWS], a1[R_ROWS];
#pragma unroll
        for (int r = 0; r < R_ROWS; r++) {
            a0[r] = *reinterpret_cast<const ulonglong2*>(aS + r * K + kb * 4);
            a1[r] = *reinterpret_cast<const ulonglong2*>(aS + r * K + kb * 4 + 2);
        }
        ulonglong2 wv[4];
#pragma unroll
        for (int kk = 0; kk < 4; kk++)
            wv[kk] = __ldg(reinterpret_cast<const ulonglong2*>(Wp + (kb * 4 + kk) * MLPW));
#pragma unroll
        for (int r = 0; r < R_ROWS; r++) {
            acc[r][0] = fma2(a0[r].x, wv[0].x, acc[r][0]);
            acc[r][1] = fma2(a0[r].x, wv[0].y, acc[r][1]);
            acc[r][0] = fma2(a0[r].y, wv[1].x, acc[r][0]);
            acc[r][1] = fma2(a0[r].y, wv[1].y, acc[r][1]);
            acc[r][0] = fma2(a1[r].x, wv[2].x, acc[r][0]);
            acc[r][1] = fma2(a1[r].x, wv[2].y, acc[r][1]);
            acc[r][0] = fma2(a1[r].y, wv[3].x, acc[r][0]);
            acc[r][1] = fma2(a1[r].y, wv[3].y, acc[r][1]);
        }
    }
}

// Output layer: N=64, lane owns cols (2l,2l+1) -> one packed acc per row.
template<int K>
__device__ __forceinline__ void gemm64_f2(const float* __restrict__ W,    // K x 64
                                          const ull* __restrict__ aS,
                                          ull acc[R_ROWS], int lane)
{
    const float* Wp = W + 2 * lane;
#pragma unroll 4
    for (int kb = 0; kb < K / 4; kb++) {
        ulonglong2 a0[R_ROWS], a1[R_ROWS];
#pragma unroll
        for (int r = 0; r < R_ROWS; r++) {
            a0[r] = *reinterpret_cast<const ulonglong2*>(aS + r * K + kb * 4);
            a1[r] = *reinterpret_cast<const ulonglong2*>(aS + r * K + kb * 4 + 2);
        }
        ull wv[4];
#pragma unroll
        for (int kk = 0; kk < 4; kk++)
            wv[kk] = __ldg(reinterpret_cast<const ull*>(Wp + (kb * 4 + kk) * HID));
#pragma unroll
        for (int r = 0; r < R_ROWS; r++) {
            acc[r] = fma2(a0[r].x, wv[0], acc[r]);
            acc[r] = fma2(a0[r].y, wv[1], acc[r]);
            acc[r] = fma2(a1[r].x, wv[2], acc[r]);
            acc[r] = fma2(a1[r].y, wv[3], acc[r]);
        }
    }
}

// Full MLP: tx=[t, x(64)] -> lipswish -> lipswish -> tanh.
// zhS: [R][HID] splatted input. hS: [R][MLPW] splatted scratch (used in-place
// for h1 then h2). outv[r][s] for hidden h = 2*lane + s.
__device__ __forceinline__ void mlp_eval(
    float tn,
    const float* __restrict__ W0, const float* __restrict__ b0,
    const float* __restrict__ W1, const float* __restrict__ b1,
    const float* __restrict__ Wo, const float* __restrict__ bo,
    const ull* __restrict__ zhS, ull* __restrict__ hS,
    float outv[R_ROWS][2], int lane)
{
    ull acc[R_ROWS][2];
    {   // bias + t * W0_row0
        ulonglong2 bv = __ldg(reinterpret_cast<const ulonglong2*>(b0 + 4 * lane));
        ulonglong2 w0 = __ldg(reinterpret_cast<const ulonglong2*>(W0 + 4 * lane));
        ull t2 = splat2(tn);
#pragma unroll
        for (int r = 0; r < R_ROWS; r++) {
            acc[r][0] = fma2(t2, w0.x, bv.x);
            acc[r][1] = fma2(t2, w0.y, bv.y);
        }
    }
    gemm128_f2<HID>(W0 + MLPW, zhS, acc, lane);   // rows 1..64 of W0
#pragma unroll
    for (int r = 0; r < R_ROWS; r++) {
        float2 p0 = unpack2(acc[r][0]), p1 = unpack2(acc[r][1]);
        float h0 = lipswish(p0.x), h1 = lipswish(p0.y);
        float h2 = lipswish(p1.x), h3 = lipswish(p1.y);
        ulonglong2 s0, s1;
        s0.x = splat2(h0); s0.y = splat2(h1);
        s1.x = splat2(h2); s1.y = splat2(h3);
        *reinterpret_cast<ulonglong2*>(hS + r * MLPW + 4 * lane) = s0;
        *reinterpret_cast<ulonglong2*>(hS + r * MLPW + 4 * lane + 2) = s1;
    }
    __syncwarp();

    {
        ulonglong2 bv = __ldg(reinterpret_cast<const ulonglong2*>(b1 + 4 * lane));
#pragma unroll
        for (int r = 0; r < R_ROWS; r++) { acc[r][0] = bv.x; acc[r][1] = bv.y; }
    }
    gemm128_f2<MLPW>(W1, hS, acc, lane);
    __syncwarp();   // all reads of h1 done before overwriting in place
#pragma unroll
    for (int r = 0; r < R_ROWS; r++) {
        float2 p0 = unpack2(acc[r][0]), p1 = unpack2(acc[r][1]);
        float h0 = lipswish(p0.x), h1 = lipswish(p0.y);
        float h2 = lipswish(p1.x), h3 = lipswish(p1.y);
        ulonglong2 s0, s1;
        s0.x = splat2(h0); s0.y = splat2(h1);
        s1.x = splat2(h2); s1.y = splat2(h3);
        *reinterpret_cast<ulonglong2*>(hS + r * MLPW + 4 * lane) = s0;
        *reinterpret_cast<ulonglong2*>(hS + r * MLPW + 4 * lane + 2) = s1;
    }
    __syncwarp();

    ull acc2[R_ROWS];
    {
        ull bv = __ldg(reinterpret_cast<const ull*>(bo + 2 * lane));
#pragma unroll
        for (int r = 0; r < R_ROWS; r++) acc2[r] = bv;
    }
    gemm64_f2<MLPW>(Wo, hS, acc2, lane);
#pragma unroll
    for (int r = 0; r < R_ROWS; r++) {
        float2 p = unpack2(acc2[r]);
        outv[r][0] = tanhf(p.x);
        outv[r][1] = tanhf(p.y);
    }
}

// lane (r = lane>>3, d = lane&7): ys[r][d] = rb[d] + z[r,:] @ RW[:,d]
__device__ __forceinline__ void readout_store(
    const float* __restrict__ zc,           // [R_ROWS][HID] compact z
    const float (*sRWt)[68], const float* __restrict__ sRB,
    float* __restrict__ out, int rowbase, int tIdx, float tval, int lane)
{
    const int r = lane >> 3;
    const int d = lane & 7;
    float acc = sRB[d];
#pragma unroll
    for (int hb = 0; hb < HID / 4; hb++) {
        float4 zv = *reinterpret_cast<const float4*>(zc + r * HID + hb * 4);
        float4 wv = *reinterpret_cast<const float4*>(&sRWt[d][hb * 4]);
        acc = fmaf(zv.x, wv.x, acc);
        acc = fmaf(zv.y, wv.y, acc);
        acc = fmaf(zv.z, wv.z, acc);
        acc = fmaf(zv.w, wv.w, acc);
    }
    size_t base = ((size_t)(rowbase + r) * T_STEPS + tIdx) * (DOUT + 1);
    out[base + 1 + d] = acc;
    if (d == 0) out[base] = tval;
}

__global__ void __launch_bounds__(NWARPS * 32, 1)
sde_kernel(const float* __restrict__ ts,
           const float* __restrict__ dW,
           const float* __restrict__ dW0, const float* __restrict__ db0,
           const float* __restrict__ dW1, const float* __restrict__ db1,
           const float* __restrict__ dWo, const float* __restrict__ dbo,
           const float* __restrict__ fW0, const float* __restrict__ fb0,
           const float* __restrict__ fW1, const float* __restrict__ fb1,
           const float* __restrict__ fWo, const float* __restrict__ fbo,
           const float* __restrict__ RW, const float* __restrict__ rb,
           float* __restrict__ out)
{
    __shared__ ull  sZh[NWARPS][R_ROWS][HID];    // splatted zhat: 14 KB
    __shared__ ull  sH [NWARPS][R_ROWS][MLPW];   // splatted h (in-place h1/h2): 28 KB
    __shared__ float sRWt[DOUT][68];
    __shared__ float sRB[DOUT];

    const int tid  = threadIdx.x;
    const int w    = tid >> 5;
    const int lane = tid & 31;

    for (int i = tid; i < HID * DOUT; i += blockDim.x)
        sRWt[i & 7][i >> 3] = __ldg(RW + i);     // RW is (64, 8) row-major
    if (tid < DOUT) sRB[tid] = __ldg(rb + tid);
    __syncthreads();

    const int rowbase = (blockIdx.x * NWARPS + w) * R_ROWS;
    if (rowbase >= B_SZ) return;                 // tail warps (12 of 1036) idle

    const float t0  = __ldg(ts + 0);
    const float dt  = __ldg(ts + 1) - t0;
    const float sdt = sqrtf(dt);

    float z[R_ROWS][2], zh[R_ROWS][2], f[R_ROWS][2], g[R_ROWS][2], dwc[R_ROWS][2];

    ull*  zhS = &sZh[w][0][0];
    ull*  hS  = &sH [w][0][0];
    float* zc = reinterpret_cast<float*>(hS);    // compact z for readout (aliases hS)

    const ull one2 = splat2(1.0f);
#pragma unroll
    for (int r = 0; r < R_ROWS; r++) {
        z[r][0] = z[r][1] = 1.0f;
        zh[r][0] = zh[r][1] = 1.0f;
        zhS[r * HID + 2 * lane]     = one2;
        zhS[r * HID + 2 * lane + 1] = one2;
    }
    __syncwarp();

    // f0, g0 at t = ts[0], x0 = ones
    mlp_eval(t0, dW0, db0, dW1, db1, dWo, dbo, zhS, hS, f, lane);
    __syncwarp();
    mlp_eval(t0, fW0, fb0, fW1, fb1, fWo, fbo, zhS, hS, g, lane);
    __syncwarp();

    // t = 0 readout: z = ones (write compact z over hS, now dead)
#pragma unroll
    for (int r = 0; r < R_ROWS; r++)
        *reinterpret_cast<float2*>(zc + r * HID + 2 * lane) = make_float2(1.0f, 1.0f);
    __syncwarp();
    readout_store(zc, sRWt, sRB, out, rowbase, 0, t0, lane);

    // Brownian increments for step 0 (pre-scaled by sqrt(dt))
#pragma unroll
    for (int r = 0; r < R_ROWS; r++) {
        float2 v = ldg2f(dW + (size_t)(rowbase + r) * HID + 2 * lane);
        dwc[r][0] = v.x * sdt; dwc[r][1] = v.y * sdt;
    }
    __syncwarp();

    for (int n = 0; n < NSTEP; n++) {
        const float tn = __ldg(ts + n + 1);

        // zhat_{n+1} = 2 z - zhat + f dt + g dw ; stage splatted for the MLPs
#pragma unroll
        for (int r = 0; r < R_ROWS; r++) {
#pragma unroll
            for (int s = 0; s < 2; s++)
                zh[r][s] = 2.0f * z[r][s] - zh[r][s] + f[r][s] * dt + g[r][s] * dwc[r][s];
            ulonglong2 zs;
            zs.x = splat2(zh[r][0]); zs.y = splat2(zh[r][1]);
            *reinterpret_cast<ulonglong2*>(zhS + r * HID + 2 * lane) = zs;
        }
        __syncwarp();

        float fn[R_ROWS][2], gn[R_ROWS][2];
        mlp_eval(tn, dW0, db0, dW1, db1, dWo, dbo, zhS, hS, fn, lane);
        __syncwarp();
        mlp_eval(tn, fW0, fb0, fW1, fb1, fWo, fbo, zhS, hS, gn, lane);
        __syncwarp();

        // z_{n+1} = z + 0.5 (f + fn) dt + 0.5 (g + gn) dw
#pragma unroll
        for (int r = 0; r < R_ROWS; r++) {
#pragma unroll
            for (int s = 0; s < 2; s++) {
                z[r][s] += 0.5f * (f[r][s] + fn[r][s]) * dt
                         + 0.5f * (g[r][s] + gn[r][s]) * dwc[r][s];
                f[r][s] = fn[r][s];
                g[r][s] = gn[r][s];
            }
        }

        // prefetch next step's dW
        if (n + 1 < NSTEP) {
#pragma unroll
            for (int r = 0; r < R_ROWS; r++) {
                float2 v = ldg2f(dW + ((size_t)(n + 1) * B_SZ + (rowbase + r)) * HID + 2 * lane);
                dwc[r][0] = v.x * sdt; dwc[r][1] = v.y * sdt;
            }
        }

        // compact z into (dead) hS region for the readout
#pragma unroll
        for (int r = 0; r < R_ROWS; r++)
            *reinterpret_cast<float2*>(zc + r * HID + 2 * lane) =
                make_float2(z[r][0], z[r][1]);
        __syncwarp();

        readout_store(zc, sRWt, sRB, out, rowbase, n + 1, tn, lane);
        __syncwarp();
    }
}

extern "C" void kernel_launch(void* const* d_in, const int* in_sizes, int n_in,
                              void* d_out, int out_size) {
    (void)in_sizes; (void)n_in; (void)out_size;
    const float* ts  = (const float*)d_in[0];
    // d_in[1] = batch_size (int32 scalar) — shapes are fixed constants here
    const float* dW  = (const float*)d_in[2];
    const float* dW0 = (const float*)d_in[3];
    const float* db0 = (const float*)d_in[4];
    const float* dW1 = (const float*)d_in[5];
    const float* db1 = (const float*)d_in[6];
    const float* dWo = (const float*)d_in[7];
    const float* dbo = (const float*)d_in[8];
    const float* fW0 = (const float*)d_in[9];
    const float* fb0 = (const float*)d_in[10];
    const float* fW1 = (const float*)d_in[11];
    const float* fb1 = (const float*)d_in[12];
    const float* fWo = (const float*)d_in[13];
    const float* fbo = (const float*)d_in[14];
    const float* RW  = (const float*)d_in[15];
    const float* rb  = (const float*)d_in[16];
    float* out = (float*)d_out;

    sde_kernel<<<NCTA, NWARPS * 32>>>(ts, dW,
                                      dW0, db0, dW1, db1, dWo, dbo,
                                      fW0, fb0, fW1, fb1, fWo, fbo,
                                      RW, rb, out);
}

// round 5
// speedup vs baseline: 1.3814x; 1.1788x over previous
#include <cuda_runtime.h>

namespace {
constexpr int T_STEPS = 256;
constexpr int B_SZ    = 4096;
constexpr int HID     = 64;
constexpr int MLPW    = 128;
constexpr int DOUT    = 8;
constexpr int RP      = 4;            // row-pairs per warp => 8 rows/warp
constexpr int NWARPS  = 8;            // 4 drift/diff warp-pairs per CTA
constexpr int QP      = NWARPS / 2;   // warp-pairs per CTA
constexpr int NSTEP   = 255;
constexpr int NCTA    = 128;          // 128 * 4 * 8 = 4096 rows exactly
}

using ull = unsigned long long;

struct QShm {                     // one drift/diff warp-pair's staging
    ull aIn[RP][HID];             // zhat input, row-paired       (2 KB)
    ull hD [RP][MLPW];            // drift MLP scratch + readout  (4 KB)
    ull hF [RP][MLPW];            // diff MLP scratch             (4 KB)
    ull gEx[RP][HID];             // g exchange                   (2 KB)
    ull dwS[2][RP][HID];          // sqrt(dt)*dW double buffer    (4 KB)
};                                // 16384 B

__device__ __forceinline__ ull fma2(ull a, ull b, ull c) {
    ull d; asm("fma.rn.f32x2 %0, %1, %2, %3;" : "=l"(d) : "l"(a), "l"(b), "l"(c)); return d;
}
__device__ __forceinline__ ull add2(ull a, ull b) {
    ull d; asm("add.rn.f32x2 %0, %1, %2;" : "=l"(d) : "l"(a), "l"(b)); return d;
}
__device__ __forceinline__ ull mul2(ull a, ull b) {
    ull d; asm("mul.rn.f32x2 %0, %1, %2;" : "=l"(d) : "l"(a), "l"(b)); return d;
}
__device__ __forceinline__ ull splat2(float x) {
    ull d; unsigned u = __float_as_uint(x);
    asm("mov.b64 %0, {%1, %1};" : "=l"(d) : "r"(u)); return d;
}
__device__ __forceinline__ ull pack2(float lo, float hi) {
    ull d; unsigned a = __float_as_uint(lo), b = __float_as_uint(hi);
    asm("mov.b64 %0, {%1, %2};" : "=l"(d) : "r"(a), "r"(b)); return d;
}
__device__ __forceinline__ float2 unpack2(ull v) {
    float2 r; asm("mov.b64 {%0, %1}, %2;" : "=f"(r.x), "=f"(r.y) : "l"(v)); return r;
}
__device__ __forceinline__ float4 ldg4(const float* p){ return __ldg((const float4*)p); }
__device__ __forceinline__ float2 ldg2f(const float* p){ return __ldg((const float2*)p); }
__device__ __forceinline__ float lipswish(float x){
    float s = 1.0f / (1.0f + __expf(-x)); return 0.909f * x * s;
}

// acc[p][c]: (row2p, row2p+1) for lane cols 4l..4l+3. aS row-paired, stride K.
template<int K>
__device__ __forceinline__ void gemm128_rp(const float* __restrict__ W,
                                           const ull* __restrict__ aS,
                                           ull acc[RP][4], int lane)
{
    const float* Wp = W + 4 * lane;
#pragma unroll 4
    for (int kb = 0; kb < K / 4; kb++) {
        ulonglong2 a0[RP], a1[RP];
#pragma unroll
        for (int p = 0; p < RP; p++) {
            a0[p] = *reinterpret_cast<const ulonglong2*>(aS + p * K + kb * 4);
            a1[p] = *reinterpret_cast<const ulonglong2*>(aS + p * K + kb * 4 + 2);
        }
        float4 wv[4];
#pragma unroll
        for (int kk = 0; kk < 4; kk++)
            wv[kk] = ldg4(Wp + (kb * 4 + kk) * MLPW);
#pragma unroll
        for (int kk = 0; kk < 4; kk++) {
            ull w0 = splat2(wv[kk].x), w1 = splat2(wv[kk].y);
            ull w2 = splat2(wv[kk].z), w3 = splat2(wv[kk].w);
#pragma unroll
            for (int p = 0; p < RP; p++) {
                ull av = (kk == 0) ? a0[p].x : (kk == 1) ? a0[p].y
                       : (kk == 2) ? a1[p].x : a1[p].y;
                acc[p][0] = fma2(av, w0, acc[p][0]);
                acc[p][1] = fma2(av, w1, acc[p][1]);
                acc[p][2] = fma2(av, w2, acc[p][2]);
                acc[p][3] = fma2(av, w3, acc[p][3]);
            }
        }
    }
}

// N=64 output layer: lane cols 2l..2l+1, acc[p][j].
template<int K>
__device__ __forceinline__ void gemm64_rp(const float* __restrict__ W,
                                          const ull* __restrict__ aS,
                                          ull acc[RP][2], int lane)
{
    const float* Wp = W + 2 * lane;
#pragma unroll 4
    for (int kb = 0; kb < K / 4; kb++) {
        ulonglong2 a0[RP], a1[RP];
#pragma unroll
        for (int p = 0; p < RP; p++) {
            a0[p] = *reinterpret_cast<const ulonglong2*>(aS + p * K + kb * 4);
            a1[p] = *reinterpret_cast<const ulonglong2*>(aS + p * K + kb * 4 + 2);
        }
        float2 wv[4];
#pragma unroll
        for (int kk = 0; kk < 4; kk++)
            wv[kk] = ldg2f(Wp + (kb * 4 + kk) * HID);
#pragma unroll
        for (int kk = 0; kk < 4; kk++) {
            ull w0 = splat2(wv[kk].x), w1 = splat2(wv[kk].y);
#pragma unroll
            for (int p = 0; p < RP; p++) {
                ull av = (kk == 0) ? a0[p].x : (kk == 1) ? a0[p].y
                       : (kk == 2) ? a1[p].x : a1[p].y;
                acc[p][0] = fma2(av, w0, acc[p][0]);
                acc[p][1] = fma2(av, w1, acc[p][1]);
            }
        }
    }
}

__device__ __forceinline__ void mlp_rp(
    float tn,
    const float* __restrict__ W0, const float* __restrict__ b0,
    const float* __restrict__ W1, const float* __restrict__ b1,
    const float* __restrict__ Wo, const float* __restrict__ bo,
    const ull* __restrict__ aIn, ull* __restrict__ hS,
    ull out[RP][2], int lane)
{
    ull acc[RP][4];
    {   // bias + t * W0_row0 (same for both packed rows -> splat)
        float4 bv = ldg4(b0 + 4 * lane);
        float4 w0 = ldg4(W0 + 4 * lane);
        ull i0 = splat2(fmaf(tn, w0.x, bv.x));
        ull i1 = splat2(fmaf(tn, w0.y, bv.y));
        ull i2 = splat2(fmaf(tn, w0.z, bv.z));
        ull i3 = splat2(fmaf(tn, w0.w, bv.w));
#pragma unroll
        for (int p = 0; p < RP; p++) {
            acc[p][0] = i0; acc[p][1] = i1; acc[p][2] = i2; acc[p][3] = i3;
        }
    }
    gemm128_rp<HID>(W0 + MLPW, aIn, acc, lane);   // rows 1..64 of W0
#pragma unroll
    for (int p = 0; p < RP; p++) {
        ulonglong2 s0, s1;
        { float2 v = unpack2(acc[p][0]); s0.x = pack2(lipswish(v.x), lipswish(v.y)); }
        { float2 v = unpack2(acc[p][1]); s0.y = pack2(lipswish(v.x), lipswish(v.y)); }
        { float2 v = unpack2(acc[p][2]); s1.x = pack2(lipswish(v.x), lipswish(v.y)); }
        { float2 v = unpack2(acc[p][3]); s1.y = pack2(lipswish(v.x), lipswish(v.y)); }
        *reinterpret_cast<ulonglong2*>(hS + p * MLPW + 4 * lane)     = s0;
        *reinterpret_cast<ulonglong2*>(hS + p * MLPW + 4 * lane + 2) = s1;
    }
    __syncwarp();

    {
        float4 bv = ldg4(b1 + 4 * lane);
        ull i0 = splat2(bv.x), i1 = splat2(bv.y), i2 = splat2(bv.z), i3 = splat2(bv.w);
#pragma unroll
        for (int p = 0; p < RP; p++) {
            acc[p][0] = i0; acc[p][1] = i1; acc[p][2] = i2; acc[p][3] = i3;
        }
    }
    gemm128_rp<MLPW>(W1, hS, acc, lane);
    __syncwarp();   // all lanes done reading h1 before in-place overwrite
#pragma unroll
    for (int p = 0; p < RP; p++) {
        ulonglong2 s0, s1;
        { float2 v = unpack2(acc[p][0]); s0.x = pack2(lipswish(v.x), lipswish(v.y)); }
        { float2 v = unpack2(acc[p][1]); s0.y = pack2(lipswish(v.x), lipswish(v.y)); }
        { float2 v = unpack2(acc[p][2]); s1.x = pack2(lipswish(v.x), lipswish(v.y)); }
        { float2 v = unpack2(acc[p][3]); s1.y = pack2(lipswish(v.x), lipswish(v.y)); }
        *reinterpret_cast<ulonglong2*>(hS + p * MLPW + 4 * lane)     = s0;
        *reinterpret_cast<ulonglong2*>(hS + p * MLPW + 4 * lane + 2) = s1;
    }
    __syncwarp();

    ull acc2[RP][2];
    {
        float2 bv = ldg2f(bo + 2 * lane);
        ull i0 = splat2(bv.x), i1 = splat2(bv.y);
#pragma unroll
        for (int p = 0; p < RP; p++) { acc2[p][0] = i0; acc2[p][1] = i1; }
    }
    gemm64_rp<MLPW>(Wo, hS, acc2, lane);
#pragma unroll
    for (int p = 0; p < RP; p++) {
#pragma unroll
        for (int j = 0; j < 2; j++) {
            float2 v = unpack2(acc2[p][j]);
            out[p][j] = pack2(tanhf(v.x), tanhf(v.y));
        }
    }
}

// Drift warp only. Unpacks row-paired z into compact zc (reuses hD), then
// lane (r = lane>>3 + 4*it, d = lane&7) computes readout for 8 rows.
__device__ __forceinline__ void readout_rp(
    const ull z[RP][2], float* __restrict__ zc,
    const float (*sRWt)[68], const float* __restrict__ sRB,
    float* __restrict__ out, int rowbase, int tIdx, float tval, int lane)
{
#pragma unroll
    for (int p = 0; p < RP; p++) {
        float2 v0 = unpack2(z[p][0]);     // (row2p_c0, row2p+1_c0)
        float2 v1 = unpack2(z[p][1]);
        *reinterpret_cast<float2*>(zc + (2 * p) * HID + 2 * lane)     = make_float2(v0.x, v1.x);
        *reinterpret_cast<float2*>(zc + (2 * p + 1) * HID + 2 * lane) = make_float2(v0.y, v1.y);
    }
    __syncwarp();
    const int d = lane & 7;
#pragma unroll
    for (int it = 0; it < 2; it++) {
        const int r = (lane >> 3) + 4 * it;
        float acc = sRB[d];
#pragma unroll
        for (int hb = 0; hb < HID / 4; hb++) {
            float4 zv = *reinterpret_cast<const float4*>(zc + r * HID + hb * 4);
            float4 wv = *reinterpret_cast<const float4*>(&sRWt[d][hb * 4]);
            acc = fmaf(zv.x, wv.x, acc);
            acc = fmaf(zv.y, wv.y, acc);
            acc = fmaf(zv.z, wv.z, acc);
            acc = fmaf(zv.w, wv.w, acc);
        }
        size_t base = ((size_t)(rowbase + r) * T_STEPS + tIdx) * (DOUT + 1);
        out[base + 1 + d] = acc;
        if (d == 0) out[base] = tval;
    }
    __syncwarp();   // zc (hD) reads done before next MLP overwrites it
}

__global__ void __launch_bounds__(NWARPS * 32, 1)
sde_kernel(const float* __restrict__ ts,
           const float* __restrict__ dW,
           const float* __restrict__ dW0, const float* __restrict__ db0,
           const float* __restrict__ dW1, const float* __restrict__ db1,
           const float* __restrict__ dWo, const float* __restrict__ dbo,
           const float* __restrict__ fW0, const float* __restrict__ fb0,
           const float* __restrict__ fW1, const float* __restrict__ fb1,
           const float* __restrict__ fWo, const float* __restrict__ fbo,
           const float* __restrict__ RW, const float* __restrict__ rb,
           float* __restrict__ out)
{
    extern __shared__ char dyn[];
    QShm* Q = reinterpret_cast<QShm*>(dyn);
    float (*sRWt)[68] = reinterpret_cast<float(*)[68]>(dyn + QP * sizeof(QShm));
    float* sRB = reinterpret_cast<float*>(dyn + QP * sizeof(QShm) + DOUT * 68 * sizeof(float));

    const int tid  = threadIdx.x;
    const int w    = tid >> 5;
    const int lane = tid & 31;
    const int q    = w >> 1;
    const bool isDrift = (w & 1) == 0;
    QShm& S = Q[q];
    ull* hS = isDrift ? &S.hD[0][0] : &S.hF[0][0];
    const int rowbase = (blockIdx.x * QP + q) * (2 * RP);

    for (int i = tid; i < HID * DOUT; i += blockDim.x)
        sRWt[i & 7][i >> 3] = __ldg(RW + i);        // RW is (64, 8) row-major
    if (tid < DOUT) sRB[tid] = __ldg(rb + tid);

    const float t0  = __ldg(ts + 0);
    const float dt  = __ldg(ts + 1) - t0;
    const float sdt = sqrtf(dt);
    const ull dt2   = splat2(dt);
    const ull hdt2  = splat2(0.5f * dt);
    const ull half2 = splat2(0.5f);
    const ull two2  = splat2(2.0f);
    const ull one2  = splat2(1.0f);
    constexpr ull SGN2 = 0x8000000080000000ULL;

    const float* W0 = isDrift ? dW0 : fW0; const float* b0 = isDrift ? db0 : fb0;
    const float* W1 = isDrift ? dW1 : fW1; const float* b1 = isDrift ? db1 : fb1;
    const float* Wo = isDrift ? dWo : fWo; const float* bo = isDrift ? dbo : fbo;

    ull z[RP][2], zh[RP][2], fq[RP][2], g[RP][2], res[RP][2];

    if (isDrift) {
#pragma unroll
        for (int p = 0; p < RP; p++) {
            z[p][0] = z[p][1] = one2;
            zh[p][0] = zh[p][1] = one2;
            ulonglong2 o; o.x = one2; o.y = one2;
            *reinterpret_cast<ulonglong2*>(&S.aIn[p][2 * lane]) = o;
        }
    } else {
        // stage sqrt(dt)*dW for step 0 into buffer 0
#pragma unroll
        for (int p = 0; p < RP; p++) {
            float2 a = ldg2f(dW + (size_t)(rowbase + 2 * p)     * HID + 2 * lane);
            float2 b = ldg2f(dW + (size_t)(rowbase + 2 * p + 1) * HID + 2 * lane);
            ulonglong2 v;
            v.x = pack2(a.x * sdt, b.x * sdt);
            v.y = pack2(a.y * sdt, b.y * sdt);
            *reinterpret_cast<ulonglong2*>(&S.dwS[0][p][2 * lane]) = v;
        }
    }
    __syncthreads();

    // f0 / g0 at t = ts[0], x0 = ones
    mlp_rp(t0, W0, b0, W1, b1, Wo, bo, &S.aIn[0][0], hS, res, lane);
    if (!isDrift) {
#pragma unroll
        for (int p = 0; p < RP; p++) {
            ulonglong2 v; v.x = res[p][0]; v.y = res[p][1];
            *reinterpret_cast<ulonglong2*>(&S.gEx[p][2 * lane]) = v;
        }
    }
    __syncthreads();

    if (isDrift) {
#pragma unroll
        for (int p = 0; p < RP; p++) {
            fq[p][0] = res[p][0]; fq[p][1] = res[p][1];
            ulonglong2 v = *reinterpret_cast<const ulonglong2*>(&S.gEx[p][2 * lane]);
            g[p][0] = v.x; g[p][1] = v.y;
        }
        readout_rp(z, reinterpret_cast<float*>(&S.hD[0][0]), sRWt, sRB,
                   out, rowbase, 0, t0, lane);   // z = ones
    }

    for (int n = 0; n < NSTEP; n++) {
        const float tn = __ldg(ts + n + 1);

        if (isDrift) {
            // zhat_{n+1} = 2z - zhat + f dt + g dw ; stage row-paired
#pragma unroll
            for (int p = 0; p < RP; p++) {
                ulonglong2 dwv = *reinterpret_cast<const ulonglong2*>(&S.dwS[n & 1][p][2 * lane]);
                ull dwp[2] = { dwv.x, dwv.y };
#pragma unroll
                for (int j = 0; j < 2; j++) {
                    ull t1 = fma2(two2, z[p][j], zh[p][j] ^ SGN2);
                    t1 = fma2(fq[p][j], dt2, t1);
                    zh[p][j] = fma2(g[p][j], dwp[j], t1);
                }
                ulonglong2 o; o.x = zh[p][0]; o.y = zh[p][1];
                *reinterpret_cast<ulonglong2*>(&S.aIn[p][2 * lane]) = o;
            }
        }
        __syncthreads();   // B1: aIn ready

        mlp_rp(tn, W0, b0, W1, b1, Wo, bo, &S.aIn[0][0], hS, res, lane);

        if (!isDrift) {
#pragma unroll
            for (int p = 0; p < RP; p++) {
                ulonglong2 v; v.x = res[p][0]; v.y = res[p][1];
                *reinterpret_cast<ulonglong2*>(&S.gEx[p][2 * lane]) = v;
            }
            // stage next step's Brownian increments into the other buffer
            const int m = (n + 1 < NSTEP) ? (n + 1) : (NSTEP - 1);
#pragma unroll
            for (int p = 0; p < RP; p++) {
                float2 a = ldg2f(dW + ((size_t)m * B_SZ + rowbase + 2 * p)     * HID + 2 * lane);
                float2 b = ldg2f(dW + ((size_t)m * B_SZ + rowbase + 2 * p + 1) * HID + 2 * lane);
                ulonglong2 v;
                v.x = pack2(a.x * sdt, b.x * sdt);
                v.y = pack2(a.y * sdt, b.y * sdt);
                *reinterpret_cast<ulonglong2*>(&S.dwS[(n + 1) & 1][p][2 * lane]) = v;
            }
        }
        __syncthreads();   // B2: gEx (and next dwS) ready

        if (isDrift) {
#pragma unroll
            for (int p = 0; p < RP; p++) {
                ulonglong2 gv = *reinterpret_cast<const ulonglong2*>(&S.gEx[p][2 * lane]);
                ulonglong2 dwv = *reinterpret_cast<const ulonglong2*>(&S.dwS[n & 1][p][2 * lane]);
                ull gn[2] = { gv.x, gv.y };
                ull dwp[2] = { dwv.x, dwv.y };
#pragma unroll
                for (int j = 0; j < 2; j++) {
                    ull s1 = add2(fq[p][j], res[p][j]);
                    z[p][j] = fma2(s1, hdt2, z[p][j]);
                    ull s2 = mul2(add2(g[p][j], gn[j]), half2);
                    z[p][j] = fma2(s2, dwp[j], z[p][j]);
                    fq[p][j] = res[p][j];
                    g[p][j]  = gn[j];
                }
            }
            readout_rp(z, reinterpret_cast<float*>(&S.hD[0][0]), sRWt, sRB,
                       out, rowbase, n + 1, tn, lane);
        }
    }
}

extern "C" void kernel_launch(void* const* d_in, const int* in_sizes, int n_in,
                              void* d_out, int out_size) {
    (void)in_sizes; (void)n_in; (void)out_size;
    const float* ts  = (const float*)d_in[0];
    // d_in[1] = batch_size (int32 scalar) — shapes are fixed constants here
    const float* dW  = (const float*)d_in[2];
    const float* dW0 = (const float*)d_in[3];
    const float* db0 = (const float*)d_in[4];
    const float* dW1 = (const float*)d_in[5];
    const float* db1 = (const float*)d_in[6];
    const float* dWo = (const float*)d_in[7];
    const float* dbo = (const float*)d_in[8];
    const float* fW0 = (const float*)d_in[9];
    const float* fb0 = (const float*)d_in[10];
    const float* fW1 = (const float*)d_in[11];
    const float* fb1 = (const float*)d_in[12];
    const float* fWo = (const float*)d_in[13];
    const float* fbo = (const float*)d_in[14];
    const float* RW  = (const float*)d_in[15];
    const float* rb  = (const float*)d_in[16];
    float* out = (float*)d_out;

    const int smem = QP * (int)sizeof(QShm) + DOUT * 68 * (int)sizeof(float) + 64;
    cudaFuncSetAttribute(sde_kernel, cudaFuncAttributeMaxDynamicSharedMemorySize, smem);

    sde_kernel<<<NCTA, NWARPS * 32, smem>>>(ts, dW,
                                            dW0, db0, dW1, db1, dWo, dbo,
                                            fW0, fb0, fW1, fb1, fWo, fbo,
                                            RW, rb, out);
}

// round 6
// speedup vs baseline: 1.4900x; 1.0787x over previous
#include <cuda_runtime.h>

namespace {
constexpr int T_STEPS = 256;
constexpr int B_SZ    = 4096;
constexpr int HID     = 64;
constexpr int MLPW    = 128;
constexpr int DOUT    = 8;
constexpr int RP      = 2;            // row-pairs per warp => 4 rows/warp
constexpr int NWARPS  = 16;           // 8 drift/diff warp-pairs per CTA
constexpr int QP      = NWARPS / 2;   // warp-pairs per CTA
constexpr int NSTEP   = 255;
constexpr int NCTA    = 128;          // 128 * 8 * 4 = 4096 rows exactly
}

using ull = unsigned long long;

struct QShm {                     // one drift/diff warp-pair's staging
    ull aIn[RP][HID];             // zhat input, row-paired       (1 KB)
    ull hD [RP][MLPW];            // drift MLP scratch + readout  (2 KB)
    ull hF [RP][MLPW];            // diff MLP scratch             (2 KB)
    ull gEx[RP][HID];             // g exchange                   (1 KB)
    ull dwS[2][RP][HID];          // sqrt(dt)*dW double buffer    (2 KB)
};                                // 8192 B

__device__ __forceinline__ ull fma2(ull a, ull b, ull c) {
    ull d; asm("fma.rn.f32x2 %0, %1, %2, %3;" : "=l"(d) : "l"(a), "l"(b), "l"(c)); return d;
}
__device__ __forceinline__ ull add2(ull a, ull b) {
    ull d; asm("add.rn.f32x2 %0, %1, %2;" : "=l"(d) : "l"(a), "l"(b)); return d;
}
__device__ __forceinline__ ull mul2(ull a, ull b) {
    ull d; asm("mul.rn.f32x2 %0, %1, %2;" : "=l"(d) : "l"(a), "l"(b)); return d;
}
__device__ __forceinline__ ull splat2(float x) {
    ull d; unsigned u = __float_as_uint(x);
    asm("mov.b64 %0, {%1, %1};" : "=l"(d) : "r"(u)); return d;
}
__device__ __forceinline__ ull pack2(float lo, float hi) {
    ull d; unsigned a = __float_as_uint(lo), b = __float_as_uint(hi);
    asm("mov.b64 %0, {%1, %2};" : "=l"(d) : "r"(a), "r"(b)); return d;
}
__device__ __forceinline__ float2 unpack2(ull v) {
    float2 r; asm("mov.b64 {%0, %1}, %2;" : "=f"(r.x), "=f"(r.y) : "l"(v)); return r;
}
__device__ __forceinline__ float4 ldg4(const float* p){ return __ldg((const float4*)p); }
__device__ __forceinline__ float2 ldg2f(const float* p){ return __ldg((const float2*)p); }
__device__ __forceinline__ float lipswish(float x){
    float s = 1.0f / (1.0f + __expf(-x)); return 0.909f * x * s;
}
// pairwise barrier: the 2 warps (64 threads) of pair q only
__device__ __forceinline__ void pair_sync(int q) {
    asm volatile("bar.sync %0, 64;" :: "r"(q + 1) : "memory");
}

// acc[p][c]: (row2p, row2p+1) for lane cols 4l..4l+3. aS row-paired, stride K.
template<int K>
__device__ __forceinline__ void gemm128_rp(const float* __restrict__ W,
                                           const ull* __restrict__ aS,
                                           ull acc[RP][4], int lane)
{
    const float* Wp = W + 4 * lane;
#pragma unroll 4
    for (int kb = 0; kb < K / 4; kb++) {
        ulonglong2 a0[RP], a1[RP];
#pragma unroll
        for (int p = 0; p < RP; p++) {
            a0[p] = *reinterpret_cast<const ulonglong2*>(aS + p * K + kb * 4);
            a1[p] = *reinterpret_cast<const ulonglong2*>(aS + p * K + kb * 4 + 2);
        }
        float4 wv[4];
#pragma unroll
        for (int kk = 0; kk < 4; kk++)
            wv[kk] = ldg4(Wp + (kb * 4 + kk) * MLPW);
#pragma unroll
        for (int kk = 0; kk < 4; kk++) {
            ull w0 = splat2(wv[kk].x), w1 = splat2(wv[kk].y);
            ull w2 = splat2(wv[kk].z), w3 = splat2(wv[kk].w);
#pragma unroll
            for (int p = 0; p < RP; p++) {
                ull av = (kk == 0) ? a0[p].x : (kk == 1) ? a0[p].y
                       : (kk == 2) ? a1[p].x : a1[p].y;
                acc[p][0] = fma2(av, w0, acc[p][0]);
                acc[p][1] = fma2(av, w1, acc[p][1]);
                acc[p][2] = fma2(av, w2, acc[p][2]);
                acc[p][3] = fma2(av, w3, acc[p][3]);
            }
        }
    }
}

// N=64 output layer: lane cols 2l..2l+1, acc[p][j].
template<int K>
__device__ __forceinline__ void gemm64_rp(const float* __restrict__ W,
                                          const ull* __restrict__ aS,
                                          ull acc[RP][2], int lane)
{
    const float* Wp = W + 2 * lane;
#pragma unroll 4
    for (int kb = 0; kb < K / 4; kb++) {
        ulonglong2 a0[RP], a1[RP];
#pragma unroll
        for (int p = 0; p < RP; p++) {
            a0[p] = *reinterpret_cast<const ulonglong2*>(aS + p * K + kb * 4);
            a1[p] = *reinterpret_cast<const ulonglong2*>(aS + p * K + kb * 4 + 2);
        }
        float2 wv[4];
#pragma unroll
        for (int kk = 0; kk < 4; kk++)
            wv[kk] = ldg2f(Wp + (kb * 4 + kk) * HID);
#pragma unroll
        for (int kk = 0; kk < 4; kk++) {
            ull w0 = splat2(wv[kk].x), w1 = splat2(wv[kk].y);
#pragma unroll
            for (int p = 0; p < RP; p++) {
                ull av = (kk == 0) ? a0[p].x : (kk == 1) ? a0[p].y
                       : (kk == 2) ? a1[p].x : a1[p].y;
                acc[p][0] = fma2(av, w0, acc[p][0]);
                acc[p][1] = fma2(av, w1, acc[p][1]);
            }
        }
    }
}

__device__ __forceinline__ void mlp_rp(
    float tn,
    const float* __restrict__ W0, const float* __restrict__ b0,
    const float* __restrict__ W1, const float* __restrict__ b1,
    const float* __restrict__ Wo, const float* __restrict__ bo,
    const ull* __restrict__ aIn, ull* __restrict__ hS,
    ull out[RP][2], int lane)
{
    ull acc[RP][4];
    {   // bias + t * W0_row0 (same for both packed rows -> splat)
        float4 bv = ldg4(b0 + 4 * lane);
        float4 w0 = ldg4(W0 + 4 * lane);
        ull i0 = splat2(fmaf(tn, w0.x, bv.x));
        ull i1 = splat2(fmaf(tn, w0.y, bv.y));
        ull i2 = splat2(fmaf(tn, w0.z, bv.z));
        ull i3 = splat2(fmaf(tn, w0.w, bv.w));
#pragma unroll
        for (int p = 0; p < RP; p++) {
            acc[p][0] = i0; acc[p][1] = i1; acc[p][2] = i2; acc[p][3] = i3;
        }
    }
    gemm128_rp<HID>(W0 + MLPW, aIn, acc, lane);   // rows 1..64 of W0
#pragma unroll
    for (int p = 0; p < RP; p++) {
        ulonglong2 s0, s1;
        { float2 v = unpack2(acc[p][0]); s0.x = pack2(lipswish(v.x), lipswish(v.y)); }
        { float2 v = unpack2(acc[p][1]); s0.y = pack2(lipswish(v.x), lipswish(v.y)); }
        { float2 v = unpack2(acc[p][2]); s1.x = pack2(lipswish(v.x), lipswish(v.y)); }
        { float2 v = unpack2(acc[p][3]); s1.y = pack2(lipswish(v.x), lipswish(v.y)); }
        *reinterpret_cast<ulonglong2*>(hS + p * MLPW + 4 * lane)     = s0;
        *reinterpret_cast<ulonglong2*>(hS + p * MLPW + 4 * lane + 2) = s1;
    }
    __syncwarp();

    {
        float4 bv = ldg4(b1 + 4 * lane);
        ull i0 = splat2(bv.x), i1 = splat2(bv.y), i2 = splat2(bv.z), i3 = splat2(bv.w);
#pragma unroll
        for (int p = 0; p < RP; p++) {
            acc[p][0] = i0; acc[p][1] = i1; acc[p][2] = i2; acc[p][3] = i3;
        }
    }
    gemm128_rp<MLPW>(W1, hS, acc, lane);
    __syncwarp();   // all lanes done reading h1 before in-place overwrite
#pragma unroll
    for (int p = 0; p < RP; p++) {
        ulonglong2 s0, s1;
        { float2 v = unpack2(acc[p][0]); s0.x = pack2(lipswish(v.x), lipswish(v.y)); }
        { float2 v = unpack2(acc[p][1]); s0.y = pack2(lipswish(v.x), lipswish(v.y)); }
        { float2 v = unpack2(acc[p][2]); s1.x = pack2(lipswish(v.x), lipswish(v.y)); }
        { float2 v = unpack2(acc[p][3]); s1.y = pack2(lipswish(v.x), lipswish(v.y)); }
        *reinterpret_cast<ulonglong2*>(hS + p * MLPW + 4 * lane)     = s0;
        *reinterpret_cast<ulonglong2*>(hS + p * MLPW + 4 * lane + 2) = s1;
    }
    __syncwarp();

    ull acc2[RP][2];
    {
        float2 bv = ldg2f(bo + 2 * lane);
        ull i0 = splat2(bv.x), i1 = splat2(bv.y);
#pragma unroll
        for (int p = 0; p < RP; p++) { acc2[p][0] = i0; acc2[p][1] = i1; }
    }
    gemm64_rp<MLPW>(Wo, hS, acc2, lane);
#pragma unroll
    for (int p = 0; p < RP; p++) {
#pragma unroll
        for (int j = 0; j < 2; j++) {
            float2 v = unpack2(acc2[p][j]);
            out[p][j] = pack2(tanhf(v.x), tanhf(v.y));
        }
    }
}

// Drift warp only. Unpacks row-paired z into compact zc (reuses hD), then
// lane (r = lane>>3, d = lane&7) computes readout for 4 rows.
__device__ __forceinline__ void readout_rp(
    const ull z[RP][2], float* __restrict__ zc,
    const float (*sRWt)[68], const float* __restrict__ sRB,
    float* __restrict__ out, int rowbase, int tIdx, float tval, int lane)
{
#pragma unroll
    for (int p = 0; p < RP; p++) {
        float2 v0 = unpack2(z[p][0]);     // (row2p_c0, row2p+1_c0)
        float2 v1 = unpack2(z[p][1]);
        *reinterpret_cast<float2*>(zc + (2 * p) * HID + 2 * lane)     = make_float2(v0.x, v1.x);
        *reinterpret_cast<float2*>(zc + (2 * p + 1) * HID + 2 * lane) = make_float2(v0.y, v1.y);
    }
    __syncwarp();
    const int d = lane & 7;
    const int r = lane >> 3;
    float acc = sRB[d];
#pragma unroll
    for (int hb = 0; hb < HID / 4; hb++) {
        float4 zv = *reinterpret_cast<const float4*>(zc + r * HID + hb * 4);
        float4 wv = *reinterpret_cast<const float4*>(&sRWt[d][hb * 4]);
        acc = fmaf(zv.x, wv.x, acc);
        acc = fmaf(zv.y, wv.y, acc);
        acc = fmaf(zv.z, wv.z, acc);
        acc = fmaf(zv.w, wv.w, acc);
    }
    size_t base = ((size_t)(rowbase + r) * T_STEPS + tIdx) * (DOUT + 1);
    out[base + 1 + d] = acc;
    if (d == 0) out[base] = tval;
    __syncwarp();   // zc (hD) reads done before next MLP overwrites it
}

__global__ void __launch_bounds__(NWARPS * 32, 1)
sde_kernel(const float* __restrict__ ts,
           const float* __restrict__ dW,
           const float* __restrict__ dW0, const float* __restrict__ db0,
           const float* __restrict__ dW1, const float* __restrict__ db1,
           const float* __restrict__ dWo, const float* __restrict__ dbo,
           const float* __restrict__ fW0, const float* __restrict__ fb0,
           const float* __restrict__ fW1, const float* __restrict__ fb1,
           const float* __restrict__ fWo, const float* __restrict__ fbo,
           const float* __restrict__ RW, const float* __restrict__ rb,
           float* __restrict__ out)
{
    extern __shared__ char dyn[];
    QShm* Q = reinterpret_cast<QShm*>(dyn);
    float (*sRWt)[68] = reinterpret_cast<float(*)[68]>(dyn + QP * sizeof(QShm));
    float* sRB = reinterpret_cast<float*>(dyn + QP * sizeof(QShm) + DOUT * 68 * sizeof(float));

    const int tid  = threadIdx.x;
    const int w    = tid >> 5;
    const int lane = tid & 31;
    const int q    = w >> 1;
    const bool isDrift = (w & 1) == 0;
    QShm& S = Q[q];
    ull* hS = isDrift ? &S.hD[0][0] : &S.hF[0][0];
    const int rowbase = (blockIdx.x * QP + q) * (2 * RP);

    for (int i = tid; i < HID * DOUT; i += blockDim.x)
        sRWt[i & 7][i >> 3] = __ldg(RW + i);        // RW is (64, 8) row-major
    if (tid < DOUT) sRB[tid] = __ldg(rb + tid);

    const float t0  = __ldg(ts + 0);
    const float dt  = __ldg(ts + 1) - t0;
    const float sdt = sqrtf(dt);
    const ull dt2   = splat2(dt);
    const ull hdt2  = splat2(0.5f * dt);
    const ull half2 = splat2(0.5f);
    const ull two2  = splat2(2.0f);
    const ull one2  = splat2(1.0f);
    constexpr ull SGN2 = 0x8000000080000000ULL;

    const float* W0 = isDrift ? dW0 : fW0; const float* b0 = isDrift ? db0 : fb0;
    const float* W1 = isDrift ? dW1 : fW1; const float* b1 = isDrift ? db1 : fb1;
    const float* Wo = isDrift ? dWo : fWo; const float* bo = isDrift ? dbo : fbo;

    ull z[RP][2], zh[RP][2], fq[RP][2], g[RP][2], res[RP][2];

    if (isDrift) {
#pragma unroll
        for (int p = 0; p < RP; p++) {
            z[p][0] = z[p][1] = one2;
            zh[p][0] = zh[p][1] = one2;
            ulonglong2 o; o.x = one2; o.y = one2;
            *reinterpret_cast<ulonglong2*>(&S.aIn[p][2 * lane]) = o;
        }
    } else {
        // stage sqrt(dt)*dW for step 0 into buffer 0
#pragma unroll
        for (int p = 0; p < RP; p++) {
            float2 a = ldg2f(dW + (size_t)(rowbase + 2 * p)     * HID + 2 * lane);
            float2 b = ldg2f(dW + (size_t)(rowbase + 2 * p + 1) * HID + 2 * lane);
            ulonglong2 v;
            v.x = pack2(a.x * sdt, b.x * sdt);
            v.y = pack2(a.y * sdt, b.y * sdt);
            *reinterpret_cast<ulonglong2*>(&S.dwS[0][p][2 * lane]) = v;
        }
    }
    __syncthreads();   // sRWt + initial staging visible block-wide (once)

    // f0 / g0 at t = ts[0], x0 = ones
    mlp_rp(t0, W0, b0, W1, b1, Wo, bo, &S.aIn[0][0], hS, res, lane);
    if (!isDrift) {
#pragma unroll
        for (int p = 0; p < RP; p++) {
            ulonglong2 v; v.x = res[p][0]; v.y = res[p][1];
            *reinterpret_cast<ulonglong2*>(&S.gEx[p][2 * lane]) = v;
        }
    }
    pair_sync(q);

    if (isDrift) {
#pragma unroll
        for (int p = 0; p < RP; p++) {
            fq[p][0] = res[p][0]; fq[p][1] = res[p][1];
            ulonglong2 v = *reinterpret_cast<const ulonglong2*>(&S.gEx[p][2 * lane]);
            g[p][0] = v.x; g[p][1] = v.y;
        }
        readout_rp(z, reinterpret_cast<float*>(&S.hD[0][0]), sRWt, sRB,
                   out, rowbase, 0, t0, lane);   // z = ones
    }

    for (int n = 0; n < NSTEP; n++) {
        const float tn = __ldg(ts + n + 1);

        if (isDrift) {
            // zhat_{n+1} = 2z - zhat + f dt + g dw ; stage row-paired
#pragma unroll
            for (int p = 0; p < RP; p++) {
                ulonglong2 dwv = *reinterpret_cast<const ulonglong2*>(&S.dwS[n & 1][p][2 * lane]);
                ull dwp[2] = { dwv.x, dwv.y };
#pragma unroll
                for (int j = 0; j < 2; j++) {
                    ull t1 = fma2(two2, z[p][j], zh[p][j] ^ SGN2);
                    t1 = fma2(fq[p][j], dt2, t1);
                    zh[p][j] = fma2(g[p][j], dwp[j], t1);
                }
                ulonglong2 o; o.x = zh[p][0]; o.y = zh[p][1];
                *reinterpret_cast<ulonglong2*>(&S.aIn[p][2 * lane]) = o;
            }
        }
        pair_sync(q);      // B1: aIn ready

        mlp_rp(tn, W0, b0, W1, b1, Wo, bo, &S.aIn[0][0], hS, res, lane);

        if (!isDrift) {
#pragma unroll
            for (int p = 0; p < RP; p++) {
                ulonglong2 v; v.x = res[p][0]; v.y = res[p][1];
                *reinterpret_cast<ulonglong2*>(&S.gEx[p][2 * lane]) = v;
            }
            // stage next step's Brownian increments into the other buffer
            const int m = (n + 1 < NSTEP) ? (n + 1) : (NSTEP - 1);
#pragma unroll
            for (int p = 0; p < RP; p++) {
                float2 a = ldg2f(dW + ((size_t)m * B_SZ + rowbase + 2 * p)     * HID + 2 * lane);
                float2 b = ldg2f(dW + ((size_t)m * B_SZ + rowbase + 2 * p + 1) * HID + 2 * lane);
                ulonglong2 v;
                v.x = pack2(a.x * sdt, b.x * sdt);
                v.y = pack2(a.y * sdt, b.y * sdt);
                *reinterpret_cast<ulonglong2*>(&S.dwS[(n + 1) & 1][p][2 * lane]) = v;
            }
        }
        pair_sync(q);      // B2: gEx (and next dwS) ready

        if (isDrift) {
#pragma unroll
            for (int p = 0; p < RP; p++) {
                ulonglong2 gv = *reinterpret_cast<const ulonglong2*>(&S.gEx[p][2 * lane]);
                ulonglong2 dwv = *reinterpret_cast<const ulonglong2*>(&S.dwS[n & 1][p][2 * lane]);
                ull gn[2] = { gv.x, gv.y };
                ull dwp[2] = { dwv.x, dwv.y };
#pragma unroll
                for (int j = 0; j < 2; j++) {
                    ull s1 = add2(fq[p][j], res[p][j]);
                    z[p][j] = fma2(s1, hdt2, z[p][j]);
                    ull s2 = mul2(add2(g[p][j], gn[j]), half2);
                    z[p][j] = fma2(s2, dwp[j], z[p][j]);
                    fq[p][j] = res[p][j];
                    g[p][j]  = gn[j];
                }
            }
            readout_rp(z, reinterpret_cast<float*>(&S.hD[0][0]), sRWt, sRB,
                       out, rowbase, n + 1, tn, lane);
        }
    }
}

extern "C" void kernel_launch(void* const* d_in, const int* in_sizes, int n_in,
                              void* d_out, int out_size) {
    (void)in_sizes; (void)n_in; (void)out_size;
    const float* ts  = (const float*)d_in[0];
    // d_in[1] = batch_size (int32 scalar) — shapes are fixed constants here
    const float* dW  = (const float*)d_in[2];
    const float* dW0 = (const float*)d_in[3];
    const float* db0 = (const float*)d_in[4];
    const float* dW1 = (const float*)d_in[5];
    const float* db1 = (const float*)d_in[6];
    const float* dWo = (const float*)d_in[7];
    const float* dbo = (const float*)d_in[8];
    const float* fW0 = (const float*)d_in[9];
    const float* fb0 = (const float*)d_in[10];
    const float* fW1 = (const float*)d_in[11];
    const float* fb1 = (const float*)d_in[12];
    const float* fWo = (const float*)d_in[13];
    const float* fbo = (const float*)d_in[14];
    const float* RW  = (const float*)d_in[15];
    const float* rb  = (const float*)d_in[16];
    float* out = (float*)d_out;

    const int smem = QP * (int)sizeof(QShm) + DOUT * 68 * (int)sizeof(float) + 64;
    cudaFuncSetAttribute(sde_kernel, cudaFuncAttributeMaxDynamicSharedMemorySize, smem);

    sde_kernel<<<NCTA, NWARPS * 32, smem>>>(ts, dW,
                                            dW0, db0, dW1, db1, dWo, dbo,
                                            fW0, fb0, fW1, fb1, fWo, fbo,
                                            RW, rb, out);
}